// round 15
// baseline (speedup 1.0000x reference)
#include <cuda_runtime.h>
#include <math.h>

#define Bn 512
#define Jn 101
#define Mn 50
#define En 128
#define Dn 60
#define DP 64
#define Pn 5120
#define TPB 768
#define NW  (TPB/32)
#define GRID 148
#define TVS 132          // activation row stride in u32 (≡4 mod 32: conflict-free mma A loads)
#define WS72 72          // weight row stride for mma B loads

typedef unsigned long long u64;
typedef unsigned int u32;

__device__ __forceinline__ void ffma2(u64& d, u64 a, u64 b) {
    asm("fma.rn.f32x2 %0, %1, %2, %0;" : "+l"(d) : "l"(a), "l"(b));
}
__device__ __forceinline__ u64 pack2(float lo, float hi) {
    u64 r; asm("mov.b64 %0, {%1,%2};" : "=l"(r) : "f"(lo), "f"(hi)); return r;
}
__device__ __forceinline__ float psum(u64 v) {
    float lo, hi; asm("mov.b64 {%0,%1}, %2;" : "=f"(lo), "=f"(hi) : "l"(v));
    return lo + hi;
}
__device__ __forceinline__ u32 f2tf(float f) {
    u32 r; asm("cvt.rna.tf32.f32 %0, %1;" : "=r"(r) : "f"(f)); return r;
}
__device__ __forceinline__ void mma_tf32(float* c, u32 a0, u32 a1, u32 a2, u32 a3,
                                         u32 b0, u32 b1) {
    asm("mma.sync.aligned.m16n8k8.row.col.f32.tf32.tf32.f32 "
        "{%0,%1,%2,%3}, {%4,%5,%6,%7}, {%8,%9}, {%0,%1,%2,%3};"
        : "+f"(c[0]), "+f"(c[1]), "+f"(c[2]), "+f"(c[3])
        : "r"(a0), "r"(a1), "r"(a2), "r"(a3), "r"(b0), "r"(b1));
}

// ---------------- device scratch ----------------
__device__ u32   g_Wtf[En * En];   // tf32 bits of Wft: [k*128 + e] = (R_w@Bc_w)[e][k]
__device__ float g_bf[En];         // R_w @ Bc_b + R_b
__device__ float g_mask[Bn * Mn];  // 0 or -inf

__global__ void k_prep(const float* __restrict__ Bc_w, const float* __restrict__ Bc_b,
                       const float* __restrict__ R_w, const float* __restrict__ R_b)
{
    int e = blockIdx.x;
    int k = threadIdx.x;
    float acc = 0.f;
    for (int j = 0; j < En; j++)
        acc += R_w[e * En + j] * Bc_w[j * En + k];
    g_Wtf[k * En + e] = f2tf(acc);
    if (k == 0) {
        float s = R_b[e];
        for (int j = 0; j < En; j++) s += R_w[e * En + j] * Bc_b[j];
        g_bf[e] = s;
    }
}

__global__ void k_mask_init()
{
    int i = blockIdx.x * blockDim.x + threadIdx.x;
    if (i < Bn * Mn) g_mask[i] = 0.f;
}

__global__ void k_mask_scatter(const int* __restrict__ pad)
{
    int i = blockIdx.x * blockDim.x + threadIdx.x;
    if (i < Pn) {
        int b = pad[i];
        int m = pad[Pn + i];
        if (b >= 0 && b < Bn && m >= 0 && m < Mn)
            g_mask[b * Mn + m] = -INFINITY;
    }
}

// ---------------- smem layout (float offsets) ----------------
#define OFF_TV    0        // 112 rows * 132 = 14784 u32 (wat scratch overlay in phase 3)
#define OFF_SU    14784    // 64 rows * 132 = 8448 u32
#define OFF_TPN   23232    // 101*64 = 6464
#define OFF_CU    29696    // 50*128 = 6400
#define OFF_ATW   36096    // 128*72 = 9216 (tf32 bits, B-layout [k][d])
#define OFF_ACW   45312    // 9216
#define OFF_CPT2  54528    // 30 d2 * 50 m * 2 = 3000
#define OFF_BFV   57528    // 128
#define OFF_ATB   57656    // 64
#define OFF_ACB   57720    // 64
#define OFF_MSK   57784    // 64
#define OFF_IDS   57848    // ints: jids 112 + cids 64
#define SMEM_FLOATS (OFF_IDS + 176)
#define SMEM_BYTES  (SMEM_FLOATS * 4)

__device__ __forceinline__ float wredsum(float v) {
    #pragma unroll
    for (int o = 16; o > 0; o >>= 1) v += __shfl_xor_sync(0xffffffffu, v, o);
    return v;
}
__device__ __forceinline__ float wredmax(float v) {
    #pragma unroll
    for (int o = 16; o > 0; o >>= 1) v = fmaxf(v, __shfl_xor_sync(0xffffffffu, v, o));
    return v;
}

__global__ __launch_bounds__(TPB, 1) void k_main(
    const int* __restrict__ titems, const int* __restrict__ citems,
    const float* __restrict__ t_emb, const float* __restrict__ c_emb,
    const float* __restrict__ Ac_w, const float* __restrict__ Ac_b,
    const float* __restrict__ At_w, const float* __restrict__ At_b,
    float* __restrict__ out)
{
    extern __shared__ float sm[];
    u32*   tvU   = (u32*)(sm + OFF_TV);     // tf32 bits, stride TVS
    u32*   suU   = (u32*)(sm + OFF_SU);     // tf32 bits, stride TVS
    float* tpn   = sm + OFF_TPN;
    float* cu    = sm + OFF_CU;
    u32*   atwU  = (u32*)(sm + OFF_ATW);
    u32*   acwU  = (u32*)(sm + OFF_ACW);
    u64*   cpt2  = (u64*)(sm + OFF_CPT2);   // [d2*Mn + m]
    float* bfv   = sm + OFF_BFV;
    float* atb   = sm + OFF_ATB;
    float* acb   = sm + OFF_ACB;
    float* mskf  = sm + OFF_MSK;
    int*   jids  = (int*)(sm + OFF_IDS);
    int*   cids  = jids + 112;

    const int tid = threadIdx.x;
    const int w   = tid >> 5, l = tid & 31;
    const int qg  = l >> 2;      // lane/4 (fragment row group)
    const int qt  = l & 3;       // lane%4

    // ======== stage weights ONCE per CTA (tf32 B-layout [k][d], stride 72) ========
    if (tid < DP) {
        atb[tid] = (tid < Dn) ? At_b[tid] : 0.f;
        acb[tid] = (tid < Dn) ? Ac_b[tid] : 0.f;
    }
    if (tid < En) bfv[tid] = g_bf[tid];
    for (int i = tid; i < Dn * En; i += TPB) {
        int d = i >> 7, k = i & 127;
        atwU[k * WS72 + d] = f2tf(At_w[i]);
        acwU[k * WS72 + d] = f2tf(Ac_w[i]);
    }
    for (int i = tid; i < En * 4; i += TPB) {   // zero d = 60..63
        int k = i >> 2, d = 60 + (i & 3);
        atwU[k * WS72 + d] = 0u;
        acwU[k * WS72 + d] = 0u;
    }

    // ======== persistent batch loop ========
    for (int b = blockIdx.x; b < Bn; b += GRID) {
        __syncthreads();   // previous batch fully done

        if (tid < 112) jids[tid] = titems[b * Jn + min(tid, Jn - 1)];
        if (tid >= 128 && tid < 192) cids[tid - 128] = citems[b * Mn + min(tid - 128, Mn - 1)];
        if (tid >= 192 && tid < 192 + Mn) mskf[tid - 192] = g_mask[b * Mn + (tid - 192)];
        __syncthreads();

        // gather embeddings, converting to tf32 bits (stride TVS=132 -> 33 uint4/row)
        {
            const float4* cef = (const float4*)c_emb;
            const float4* tef = (const float4*)t_emb;
            uint4* suf = (uint4*)suU;
            uint4* tvf = (uint4*)tvU;
            for (int i = tid; i < 64 * 32; i += TPB) {
                float4 v = cef[(size_t)cids[i >> 5] * 32 + (i & 31)];
                suf[(i >> 5) * 33 + (i & 31)] = make_uint4(f2tf(v.x), f2tf(v.y), f2tf(v.z), f2tf(v.w));
            }
            for (int i = tid; i < 112 * 32; i += TPB) {
                float4 v = tef[(size_t)jids[i >> 5] * 32 + (i & 31)];
                tvf[(i >> 5) * 33 + (i & 31)] = make_uint4(f2tf(v.x), f2tf(v.y), f2tf(v.z), f2tf(v.w));
            }
        }
        __syncthreads();

        // ========== phase 2: 19 mma warps (7 tp + 4 cp + 8 cu), 128 mmas each ==========
        if (w < 11) {
            // ---- projection via tf32 mma: tile of 16 rows x 64 d ----
            const bool iscp = (w >= 7);
            const int tile  = iscp ? (w - 7) : w;
            const u32* src  = iscp ? suU : tvU;
            const u32* wb   = iscp ? acwU : atwU;
            const float* bias = iscp ? acb : atb;
            const int rA = tile * 16 + qg;
            const int rB = rA + 8;
            const u32* pA = src + rA * TVS + qt;
            const u32* pB = src + rB * TVS + qt;

            float c[8][4];
            #pragma unroll
            for (int nt = 0; nt < 8; nt++)
                #pragma unroll
                for (int j = 0; j < 4; j++) c[nt][j] = 0.f;

            #pragma unroll 4
            for (int ks = 0; ks < 16; ks++) {
                u32 a0 = pA[ks * 8];
                u32 a2 = pA[ks * 8 + 4];
                u32 a1 = pB[ks * 8];
                u32 a3 = pB[ks * 8 + 4];
                const u32* wrow0 = wb + (ks * 8 + qt) * WS72 + qg;
                const u32* wrow1 = wrow0 + 4 * WS72;
                #pragma unroll
                for (int nt = 0; nt < 8; nt++) {
                    u32 b0 = wrow0[nt * 8];
                    u32 b1 = wrow1[nt * 8];
                    mma_tf32(c[nt], a0, a1, a2, a3, b0, b1);
                }
            }
            // bias, norm (quad-reduce), normalized store
            #pragma unroll
            for (int nt = 0; nt < 8; nt++) {
                int d0 = nt * 8 + 2 * qt;
                float b0f = bias[d0], b1f = bias[d0 + 1];
                c[nt][0] += b0f; c[nt][1] += b1f;
                c[nt][2] += b0f; c[nt][3] += b1f;
            }
            float sa = 0.f, sb = 0.f;
            #pragma unroll
            for (int nt = 0; nt < 8; nt++) {
                sa += c[nt][0]*c[nt][0] + c[nt][1]*c[nt][1];
                sb += c[nt][2]*c[nt][2] + c[nt][3]*c[nt][3];
            }
            sa += __shfl_xor_sync(0xffffffffu, sa, 1);
            sa += __shfl_xor_sync(0xffffffffu, sa, 2);
            sb += __shfl_xor_sync(0xffffffffu, sb, 1);
            sb += __shfl_xor_sync(0xffffffffu, sb, 2);
            float iva = 1.f / fmaxf(sqrtf(sa), 1e-6f);
            float ivb = 1.f / fmaxf(sqrtf(sb), 1e-6f);
            if (!iscp) {
                u64* tpq = (u64*)tpn;
                #pragma unroll
                for (int nt = 0; nt < 8; nt++) {
                    if (rA < Jn) tpq[rA * 32 + nt * 4 + qt] = pack2(c[nt][0]*iva, c[nt][1]*iva);
                    if (rB < Jn) tpq[rB * 32 + nt * 4 + qt] = pack2(c[nt][2]*ivb, c[nt][3]*ivb);
                }
            } else {
                #pragma unroll
                for (int nt = 0; nt < 8; nt++) {
                    int d2 = nt * 4 + qt;
                    if (d2 < 30) {
                        if (rA < Mn) cpt2[d2 * Mn + rA] = pack2(c[nt][0]*iva, c[nt][1]*iva);
                        if (rB < Mn) cpt2[d2 * Mn + rB] = pack2(c[nt][2]*ivb, c[nt][3]*ivb);
                    }
                }
            }
        } else if (w < 19) {
            // ---- cu via tf32 mma: 1 m-tile (16 rows) x 8 n-tiles (64 e), B from L2 ----
            const int t = w - 11;            // 0..7
            const int mtile = t >> 1;        // 0..3
            const int nhalf = t & 1;         // e-half
            const int rA = mtile * 16 + qg;
            const int rB = rA + 8;
            const u32* pA = suU + rA * TVS + qt;
            const u32* pB = suU + rB * TVS + qt;

            float c[8][4];
            #pragma unroll
            for (int nt = 0; nt < 8; nt++)
                #pragma unroll
                for (int j = 0; j < 4; j++) c[nt][j] = 0.f;

            #pragma unroll 2
            for (int ks = 0; ks < 16; ks++) {
                u32 a0 = pA[ks * 8];
                u32 a2 = pA[ks * 8 + 4];
                u32 a1 = pB[ks * 8];
                u32 a3 = pB[ks * 8 + 4];
                const u32* wrow0 = g_Wtf + (ks * 8 + qt) * En + nhalf * 64 + qg;
                const u32* wrow1 = wrow0 + 4 * En;
                #pragma unroll
                for (int nt = 0; nt < 8; nt++) {
                    u32 b0 = wrow0[nt * 8];
                    u32 b1 = wrow1[nt * 8];
                    mma_tf32(c[nt], a0, a1, a2, a3, b0, b1);
                }
            }
            // store to cu (fp32 smem), rows >= Mn are clamp-padding -> skip
            u64* cuU = (u64*)cu;
            #pragma unroll
            for (int nt = 0; nt < 8; nt++) {
                int eh = nhalf * 32 + nt * 4 + qt;   // (e/2) index
                if (rA < Mn) cuU[rA * 64 + eh] = pack2(c[nt][0], c[nt][1]);
                if (rB < Mn) cuU[rB * 64 + eh] = pack2(c[nt][2], c[nt][3]);
            }
        }
        __syncthreads();

        // ========== phase 3: scores + softmax + epilogue, 5 j per warp-tile (21 tiles) ==========
        if (w < 21) {
            u64* wat = (u64*)tvU + w * 250;   // tv dead; per-warp (a,a)-packed attn
            const u64* cuU = (const u64*)cu;
            int j0 = 5 * w;
            int jj[5];
            const ulonglong2* tpV[5];
            #pragma unroll
            for (int i = 0; i < 5; i++) {
                jj[i] = min(j0 + i, Jn - 1);
                tpV[i] = (const ulonglong2*)(tpn + jj[i] * DP);
            }
            const bool act = (l < 25);
            const int m0 = act ? l : 0;
            const int m1 = m0 + 25;

            u64 s0[5], s1[5];
            #pragma unroll
            for (int i = 0; i < 5; i++) { s0[i] = 0; s1[i] = 0; }
            #pragma unroll 3
            for (int d4 = 0; d4 < 15; d4++) {
                u64 c00 = cpt2[(2*d4    ) * Mn + m0];
                u64 c01 = cpt2[(2*d4 + 1) * Mn + m0];
                u64 c10 = cpt2[(2*d4    ) * Mn + m1];
                u64 c11 = cpt2[(2*d4 + 1) * Mn + m1];
                #pragma unroll
                for (int i = 0; i < 5; i++) {
                    ulonglong2 t = tpV[i][d4];
                    ffma2(s0[i], t.x, c00); ffma2(s0[i], t.y, c01);
                    ffma2(s1[i], t.x, c10); ffma2(s1[i], t.y, c11);
                }
            }
            float mk0 = act ? mskf[m0] : -INFINITY;
            float mk1 = act ? mskf[m1] : -INFINITY;
            #pragma unroll
            for (int i = 0; i < 5; i++) {
                float v0 = psum(s0[i]) + mk0;
                float v1 = psum(s1[i]) + mk1;
                float mx = wredmax(fmaxf(v0, v1));
                float e0 = __expf(v0 - mx);
                float e1 = __expf(v1 - mx);
                float ss = wredsum(e0 + e1);
                float inv = 1.f / ss;
                if (act) {
                    float a0 = e0 * inv, a1 = e1 * inv;
                    wat[i * Mn + m0] = pack2(a0, a0);
                    wat[i * Mn + m1] = pack2(a1, a1);
                }
            }
            __syncwarp();

            const u64* bfU = (const u64*)bfv;
            u64 o01[5], o23[5];
            #pragma unroll
            for (int i = 0; i < 5; i++) { o01[i] = bfU[2 * l]; o23[i] = bfU[2 * l + 1]; }
            #pragma unroll 5
            for (int m = 0; m < Mn; m++) {
                u64 c01 = cuU[m * 64 + 2 * l];
                u64 c23 = cuU[m * 64 + 2 * l + 1];
                #pragma unroll
                for (int i = 0; i < 5; i++) {
                    u64 aa = wat[i * Mn + m];
                    ffma2(o01[i], aa, c01);
                    ffma2(o23[i], aa, c23);
                }
            }
            u64* op = (u64*)(out + (size_t)b * Jn * En);
            #pragma unroll
            for (int i = 0; i < 5; i++) {
                op[jj[i] * 64 + 2 * l]     = o01[i];
                op[jj[i] * 64 + 2 * l + 1] = o23[i];
            }
        }
    }
}

// ---------------- launch ----------------
extern "C" void kernel_launch(void* const* d_in, const int* in_sizes, int n_in,
                              void* d_out, int out_size)
{
    const int*   titems = (const int*)d_in[0];
    const int*   citems = (const int*)d_in[1];
    const int*   pad    = (const int*)d_in[2];
    const float* t_emb  = (const float*)d_in[3];
    const float* c_emb  = (const float*)d_in[4];
    const float* Ac_w   = (const float*)d_in[5];
    const float* Ac_b   = (const float*)d_in[6];
    const float* At_w   = (const float*)d_in[7];
    const float* At_b   = (const float*)d_in[8];
    const float* Bc_w   = (const float*)d_in[9];
    const float* Bc_b   = (const float*)d_in[10];
    const float* R_w    = (const float*)d_in[11];
    const float* R_b    = (const float*)d_in[12];
    float* out = (float*)d_out;

    cudaFuncSetAttribute(k_main, cudaFuncAttributeMaxDynamicSharedMemorySize, SMEM_BYTES);

    k_prep<<<En, En>>>(Bc_w, Bc_b, R_w, R_b);
    k_mask_init<<<(Bn * Mn + 255) / 256, 256>>>();
    k_mask_scatter<<<(Pn + 255) / 256, 256>>>(pad);
    k_main<<<GRID, TPB, SMEM_BYTES>>>(titems, citems, t_emb, c_emb,
                                      Ac_w, Ac_b, At_w, At_b, out);
}

// round 17
// speedup vs baseline: 1.3167x; 1.3167x over previous
#include <cuda_runtime.h>
#include <math.h>

#define Bn 512
#define Jn 101
#define Mn 50
#define En 128
#define Dn 60
#define Pn 5120
#define TPB 768
#define NW  (TPB/32)
#define GRID 148
#define TVS 132          // activation row stride in u32 (≡4 mod 32: conflict-free mma A loads)
#define WS72 72          // weight row stride for mma B loads
#define TPS 60           // tpn row stride (floats) = 30 u64
#define ATS 60           // attnS row stride (u32)
#define CUS 136          // cu row stride (u32) => conflict-free B loads

typedef unsigned long long u64;
typedef unsigned int u32;

__device__ __forceinline__ void ffma2(u64& d, u64 a, u64 b) {
    asm("fma.rn.f32x2 %0, %1, %2, %0;" : "+l"(d) : "l"(a), "l"(b));
}
__device__ __forceinline__ u64 pack2(float lo, float hi) {
    u64 r; asm("mov.b64 %0, {%1,%2};" : "=l"(r) : "f"(lo), "f"(hi)); return r;
}
__device__ __forceinline__ u64 pack2u(u32 lo, u32 hi) {
    u64 r; asm("mov.b64 %0, {%1,%2};" : "=l"(r) : "r"(lo), "r"(hi)); return r;
}
__device__ __forceinline__ float psum(u64 v) {
    float lo, hi; asm("mov.b64 {%0,%1}, %2;" : "=f"(lo), "=f"(hi) : "l"(v));
    return lo + hi;
}
__device__ __forceinline__ u32 f2tf(float f) {
    u32 r; asm("cvt.rna.tf32.f32 %0, %1;" : "=r"(r) : "f"(f)); return r;
}
__device__ __forceinline__ void mma_tf32(float* c, u32 a0, u32 a1, u32 a2, u32 a3,
                                         u32 b0, u32 b1) {
    asm("mma.sync.aligned.m16n8k8.row.col.f32.tf32.tf32.f32 "
        "{%0,%1,%2,%3}, {%4,%5,%6,%7}, {%8,%9}, {%0,%1,%2,%3};"
        : "+f"(c[0]), "+f"(c[1]), "+f"(c[2]), "+f"(c[3])
        : "r"(a0), "r"(a1), "r"(a2), "r"(a3), "r"(b0), "r"(b1));
}

// ---------------- device scratch ----------------
__device__ u32   g_Wtf[En * En];   // tf32 bits of Wft: [k*128 + e] = (R_w@Bc_w)[e][k]
__device__ float g_bf[En];         // R_w @ Bc_b + R_b
__device__ float g_mask[Bn * Mn];  // 0 or -inf

__global__ void k_prep(const float* __restrict__ Bc_w, const float* __restrict__ Bc_b,
                       const float* __restrict__ R_w, const float* __restrict__ R_b)
{
    int e = blockIdx.x;
    int k = threadIdx.x;
    float acc = 0.f;
    for (int j = 0; j < En; j++)
        acc += R_w[e * En + j] * Bc_w[j * En + k];
    g_Wtf[k * En + e] = f2tf(acc);
    if (k == 0) {
        float s = R_b[e];
        for (int j = 0; j < En; j++) s += R_w[e * En + j] * Bc_b[j];
        g_bf[e] = s;
    }
}

__global__ void k_mask_init()
{
    int i = blockIdx.x * blockDim.x + threadIdx.x;
    if (i < Bn * Mn) g_mask[i] = 0.f;
}

__global__ void k_mask_scatter(const int* __restrict__ pad)
{
    int i = blockIdx.x * blockDim.x + threadIdx.x;
    if (i < Pn) {
        int b = pad[i];
        int m = pad[Pn + i];
        if (b >= 0 && b < Bn && m >= 0 && m < Mn)
            g_mask[b * Mn + m] = -INFINITY;
    }
}

// ---------------- smem layout (float offsets) ----------------
#define OFF_TV    0        // 112 * 132 = 14784 u32 (attnS overlay in phase 3)
#define OFF_SU    14784    // 50 * 132 = 6600 u32
#define OFF_TPN   21384    // 101 * 60 = 6060
#define OFF_CU    27444    // 56 * 136 = 7616  (rows 50..55 = zero pad, IN BOUNDS now)
#define OFF_ATW   35060    // 128 * 72 = 9216 (tf32 bits, B-layout [k][d])
#define OFF_ACW   44276    // 9216
#define OFF_CPT2  53492    // 30 d2 * 50 m * 2 = 3000
#define OFF_BFV   56492    // 128
#define OFF_ATB   56620    // 64
#define OFF_ACB   56684    // 64
#define OFF_MSK   56748    // 64
#define OFF_IDS   56812    // ints: jids 112 + cids 64
#define SMEM_FLOATS (OFF_IDS + 176)
#define SMEM_BYTES  (SMEM_FLOATS * 4)    // 227,952 B <= 232,448 cap

__device__ __forceinline__ float wredsum(float v) {
    #pragma unroll
    for (int o = 16; o > 0; o >>= 1) v += __shfl_xor_sync(0xffffffffu, v, o);
    return v;
}
__device__ __forceinline__ float wredmax(float v) {
    #pragma unroll
    for (int o = 16; o > 0; o >>= 1) v = fmaxf(v, __shfl_xor_sync(0xffffffffu, v, o));
    return v;
}

__global__ __launch_bounds__(TPB, 1) void k_main(
    const int* __restrict__ titems, const int* __restrict__ citems,
    const float* __restrict__ t_emb, const float* __restrict__ c_emb,
    const float* __restrict__ Ac_w, const float* __restrict__ Ac_b,
    const float* __restrict__ At_w, const float* __restrict__ At_b,
    float* __restrict__ out)
{
    extern __shared__ float sm[];
    u32*   tvU   = (u32*)(sm + OFF_TV);     // tf32 bits, stride TVS; later attnS
    u32*   suU   = (u32*)(sm + OFF_SU);     // tf32 bits, stride TVS (50 rows)
    float* tpn   = sm + OFF_TPN;            // stride TPS
    u32*   cuU   = (u32*)(sm + OFF_CU);     // tf32 bits, stride CUS (56 rows)
    u32*   atwU  = (u32*)(sm + OFF_ATW);
    u32*   acwU  = (u32*)(sm + OFF_ACW);
    u64*   cpt2  = (u64*)(sm + OFF_CPT2);   // [d2*Mn + m]
    float* bfv   = sm + OFF_BFV;
    float* atb   = sm + OFF_ATB;
    float* acb   = sm + OFF_ACB;
    float* mskf  = sm + OFF_MSK;
    int*   jids  = (int*)(sm + OFF_IDS);
    int*   cids  = jids + 112;

    const int tid = threadIdx.x;
    const int w   = tid >> 5, l = tid & 31;
    const int qg  = l >> 2;      // lane/4 (fragment row group)
    const int qt  = l & 3;       // lane%4

    // ======== stage weights ONCE per CTA (tf32 B-layout [k][d], stride 72) ========
    if (tid < 64) {
        atb[tid] = (tid < Dn) ? At_b[tid] : 0.f;
        acb[tid] = (tid < Dn) ? Ac_b[tid] : 0.f;
    }
    if (tid < En) bfv[tid] = g_bf[tid];
    for (int i = tid; i < Dn * En; i += TPB) {
        int d = i >> 7, k = i & 127;
        atwU[k * WS72 + d] = f2tf(At_w[i]);
        acwU[k * WS72 + d] = f2tf(Ac_w[i]);
    }
    for (int i = tid; i < En * 4; i += TPB) {   // zero d = 60..63
        int k = i >> 2, d = 60 + (i & 3);
        atwU[k * WS72 + d] = 0u;
        acwU[k * WS72 + d] = 0u;
    }

    // ======== persistent batch loop ========
    for (int b = blockIdx.x; b < Bn; b += GRID) {
        __syncthreads();   // previous batch's 3b done (attnS/tv reuse)

        if (tid < 112) jids[tid] = titems[b * Jn + min(tid, Jn - 1)];
        if (tid >= 128 && tid < 192) cids[tid - 128] = citems[b * Mn + min(tid - 128, Mn - 1)];
        if (tid >= 192 && tid < 192 + Mn) mskf[tid - 192] = g_mask[b * Mn + (tid - 192)];
        __syncthreads();

        // gather embeddings, converting to tf32 bits (stride TVS=132 -> 33 uint4/row)
        {
            const float4* cef = (const float4*)c_emb;
            const float4* tef = (const float4*)t_emb;
            uint4* suf = (uint4*)suU;
            uint4* tvf = (uint4*)tvU;
            for (int i = tid; i < 50 * 32; i += TPB) {
                float4 v = cef[(size_t)cids[i >> 5] * 32 + (i & 31)];
                suf[(i >> 5) * 33 + (i & 31)] = make_uint4(f2tf(v.x), f2tf(v.y), f2tf(v.z), f2tf(v.w));
            }
            for (int i = tid; i < 112 * 32; i += TPB) {
                float4 v = tef[(size_t)jids[i >> 5] * 32 + (i & 31)];
                tvf[(i >> 5) * 33 + (i & 31)] = make_uint4(f2tf(v.x), f2tf(v.y), f2tf(v.z), f2tf(v.w));
            }
        }
        __syncthreads();

        // ========== phase 2: 19 mma warps (7 tp + 4 cp + 8 cu) + pad-zero warps ==========
        if (w < 11) {
            // ---- projection via tf32 mma: tile of 16 rows x 64 d ----
            const bool iscp = (w >= 7);
            const int tile  = iscp ? (w - 7) : w;
            const u32* src  = iscp ? suU : tvU;
            const u32* wb   = iscp ? acwU : atwU;
            const float* bias = iscp ? acb : atb;
            const int rA = tile * 16 + qg;
            const int rB = rA + 8;
            // clamp su row pointers (su has 50 rows); tv has all 112 rows staged
            const int rAc = iscp ? min(rA, Mn - 1) : rA;
            const int rBc = iscp ? min(rB, Mn - 1) : rB;
            const u32* pA = src + rAc * TVS + qt;
            const u32* pB = src + rBc * TVS + qt;

            float c[8][4];
            #pragma unroll
            for (int nt = 0; nt < 8; nt++)
                #pragma unroll
                for (int j = 0; j < 4; j++) c[nt][j] = 0.f;

            #pragma unroll 4
            for (int ks = 0; ks < 16; ks++) {
                u32 a0 = pA[ks * 8];
                u32 a2 = pA[ks * 8 + 4];
                u32 a1 = pB[ks * 8];
                u32 a3 = pB[ks * 8 + 4];
                const u32* wrow0 = wb + (ks * 8 + qt) * WS72 + qg;
                const u32* wrow1 = wrow0 + 4 * WS72;
                #pragma unroll
                for (int nt = 0; nt < 8; nt++) {
                    u32 b0 = wrow0[nt * 8];
                    u32 b1 = wrow1[nt * 8];
                    mma_tf32(c[nt], a0, a1, a2, a3, b0, b1);
                }
            }
            // bias, norm (quad-reduce), normalized store
            #pragma unroll
            for (int nt = 0; nt < 8; nt++) {
                int d0 = nt * 8 + 2 * qt;
                float b0f = bias[d0], b1f = bias[d0 + 1];
                c[nt][0] += b0f; c[nt][1] += b1f;
                c[nt][2] += b0f; c[nt][3] += b1f;
            }
            float sa = 0.f, sb = 0.f;
            #pragma unroll
            for (int nt = 0; nt < 8; nt++) {
                sa += c[nt][0]*c[nt][0] + c[nt][1]*c[nt][1];
                sb += c[nt][2]*c[nt][2] + c[nt][3]*c[nt][3];
            }
            sa += __shfl_xor_sync(0xffffffffu, sa, 1);
            sa += __shfl_xor_sync(0xffffffffu, sa, 2);
            sb += __shfl_xor_sync(0xffffffffu, sb, 1);
            sb += __shfl_xor_sync(0xffffffffu, sb, 2);
            float iva = 1.f / fmaxf(sqrtf(sa), 1e-6f);
            float ivb = 1.f / fmaxf(sqrtf(sb), 1e-6f);
            if (!iscp) {
                u64* tpq = (u64*)tpn;    // row stride 30 u64
                #pragma unroll
                for (int nt = 0; nt < 8; nt++) {
                    int d2 = nt * 4 + qt;
                    if (d2 < 30) {
                        if (rA < Jn) tpq[rA * 30 + d2] = pack2(c[nt][0]*iva, c[nt][1]*iva);
                        if (rB < Jn) tpq[rB * 30 + d2] = pack2(c[nt][2]*ivb, c[nt][3]*ivb);
                    }
                }
            } else {
                #pragma unroll
                for (int nt = 0; nt < 8; nt++) {
                    int d2 = nt * 4 + qt;
                    if (d2 < 30) {
                        if (rA < Mn) cpt2[d2 * Mn + rA] = pack2(c[nt][0]*iva, c[nt][1]*iva);
                        if (rB < Mn) cpt2[d2 * Mn + rB] = pack2(c[nt][2]*ivb, c[nt][3]*ivb);
                    }
                }
            }
        } else if (w < 19) {
            // ---- cu via tf32 mma: 1 m-tile (16 rows) x 8 n-tiles (64 e), B from L2 ----
            const int t = w - 11;            // 0..7
            const int mtile = t >> 1;        // 0..3
            const int nhalf = t & 1;         // e-half
            const int rA = mtile * 16 + qg;
            const int rB = rA + 8;
            const u32* pA = suU + min(rA, Mn - 1) * TVS + qt;
            const u32* pB = suU + min(rB, Mn - 1) * TVS + qt;

            float c[8][4];
            #pragma unroll
            for (int nt = 0; nt < 8; nt++)
                #pragma unroll
                for (int j = 0; j < 4; j++) c[nt][j] = 0.f;

            #pragma unroll 2
            for (int ks = 0; ks < 16; ks++) {
                u32 a0 = pA[ks * 8];
                u32 a2 = pA[ks * 8 + 4];
                u32 a1 = pB[ks * 8];
                u32 a3 = pB[ks * 8 + 4];
                const u32* wrow0 = g_Wtf + (ks * 8 + qt) * En + nhalf * 64 + qg;
                const u32* wrow1 = wrow0 + 4 * En;
                #pragma unroll
                for (int nt = 0; nt < 8; nt++) {
                    u32 b0 = wrow0[nt * 8];
                    u32 b1 = wrow1[nt * 8];
                    mma_tf32(c[nt], a0, a1, a2, a3, b0, b1);
                }
            }
            // store tf32 bits to cu (stride CUS); rows >= Mn are clamp-padding -> skip
            u64* cuW = (u64*)cuU;     // row stride 68 u64
            #pragma unroll
            for (int nt = 0; nt < 8; nt++) {
                int eh = nhalf * 32 + nt * 4 + qt;   // (e/2) index
                if (rA < Mn) cuW[rA * 68 + eh] = pack2u(f2tf(c[nt][0]), f2tf(c[nt][1]));
                if (rB < Mn) cuW[rB * 68 + eh] = pack2u(f2tf(c[nt][2]), f2tf(c[nt][3]));
            }
        } else {
            // ---- warps 19..23: zero cu pad rows 50..55 (epilogue k-padding), IN BOUNDS ----
            for (int i = tid - 19 * 32; i < 6 * CUS; i += 5 * 32)
                cuU[50 * CUS + i] = 0u;
        }
        __syncthreads();

        // ========== phase 3a: scores + softmax -> attnS (tf32), 21 warps ==========
        u32* attnS = tvU;    // tv dead; [j][m] stride ATS=60
        if (w < 21) {
            int j0 = 5 * w;
            int jj[5];
            const ulonglong2* tpV[5];
            #pragma unroll
            for (int i = 0; i < 5; i++) {
                jj[i] = min(j0 + i, Jn - 1);
                tpV[i] = (const ulonglong2*)(tpn + jj[i] * TPS);
            }
            const bool act = (l < 25);
            const int m0 = act ? l : 0;
            const int m1 = m0 + 25;

            u64 s0[5], s1[5];
            #pragma unroll
            for (int i = 0; i < 5; i++) { s0[i] = 0; s1[i] = 0; }
            #pragma unroll 3
            for (int d4 = 0; d4 < 15; d4++) {
                u64 c00 = cpt2[(2*d4    ) * Mn + m0];
                u64 c01 = cpt2[(2*d4 + 1) * Mn + m0];
                u64 c10 = cpt2[(2*d4    ) * Mn + m1];
                u64 c11 = cpt2[(2*d4 + 1) * Mn + m1];
                #pragma unroll
                for (int i = 0; i < 5; i++) {
                    ulonglong2 t = tpV[i][d4];
                    ffma2(s0[i], t.x, c00); ffma2(s0[i], t.y, c01);
                    ffma2(s1[i], t.x, c10); ffma2(s1[i], t.y, c11);
                }
            }
            float mk0 = act ? mskf[m0] : -INFINITY;
            float mk1 = act ? mskf[m1] : -INFINITY;
            #pragma unroll
            for (int i = 0; i < 5; i++) {
                float v0 = psum(s0[i]) + mk0;
                float v1 = psum(s1[i]) + mk1;
                float mx = wredmax(fmaxf(v0, v1));
                float e0 = __expf(v0 - mx);
                float e1 = __expf(v1 - mx);
                float ss = wredsum(e0 + e1);
                float inv = 1.f / ss;
                if (act) {
                    attnS[jj[i] * ATS + m0] = f2tf(e0 * inv);
                    attnS[jj[i] * ATS + m1] = f2tf(e1 * inv);
                }
            }
        } else {
            // warps 21..23: zero attn pads (cols 50..55 rows 0..100; rows 101..111 fully)
            for (int i = tid - 21 * 32; i < 101 * 6; i += 3 * 32)
                attnS[(i / 6) * ATS + 50 + (i % 6)] = 0u;
            for (int i = tid - 21 * 32; i < 11 * ATS; i += 3 * 32)
                attnS[(101 + i / ATS) * ATS + (i % ATS)] = 0u;
        }
        __syncthreads();

        // ========== phase 3b: epilogue via tf32 mma: out = attn @ cu + bf, 14 warps ==========
        if (w < 14) {
            const int jt = w >> 1;           // 0..6
            const int nh = w & 1;            // e-half
            const int rA = jt * 16 + qg;
            const int rB = rA + 8;
            const u32* pA = attnS + rA * ATS + qt;
            const u32* pB = attnS + rB * ATS + qt;

            float c[8][4];
            #pragma unroll
            for (int nt = 0; nt < 8; nt++)
                #pragma unroll
                for (int j = 0; j < 4; j++) c[nt][j] = 0.f;

            #pragma unroll
            for (int ks = 0; ks < 7; ks++) {
                u32 a0 = pA[ks * 8];
                u32 a2 = pA[ks * 8 + 4];
                u32 a1 = pB[ks * 8];
                u32 a3 = pB[ks * 8 + 4];
                const u32* cw0 = cuU + (ks * 8 + qt) * CUS + nh * 64 + qg;
                const u32* cw1 = cw0 + 4 * CUS;
                #pragma unroll
                for (int nt = 0; nt < 8; nt++) {
                    u32 b0 = cw0[nt * 8];
                    u32 b1 = cw1[nt * 8];
                    mma_tf32(c[nt], a0, a1, a2, a3, b0, b1);
                }
            }
            u64* op = (u64*)(out + (size_t)b * Jn * En);
            #pragma unroll
            for (int nt = 0; nt < 8; nt++) {
                int e0 = nh * 64 + nt * 8 + 2 * qt;
                float b0f = bfv[e0], b1f = bfv[e0 + 1];
                int eh = e0 >> 1;
                if (rA < Jn) op[rA * 64 + eh] = pack2(c[nt][0] + b0f, c[nt][1] + b1f);
                if (rB < Jn) op[rB * 64 + eh] = pack2(c[nt][2] + b0f, c[nt][3] + b1f);
            }
        }
    }
}

// ---------------- launch ----------------
extern "C" void kernel_launch(void* const* d_in, const int* in_sizes, int n_in,
                              void* d_out, int out_size)
{
    const int*   titems = (const int*)d_in[0];
    const int*   citems = (const int*)d_in[1];
    const int*   pad    = (const int*)d_in[2];
    const float* t_emb  = (const float*)d_in[3];
    const float* c_emb  = (const float*)d_in[4];
    const float* Ac_w   = (const float*)d_in[5];
    const float* Ac_b   = (const float*)d_in[6];
    const float* At_w   = (const float*)d_in[7];
    const float* At_b   = (const float*)d_in[8];
    const float* Bc_w   = (const float*)d_in[9];
    const float* Bc_b   = (const float*)d_in[10];
    const float* R_w    = (const float*)d_in[11];
    const float* R_b    = (const float*)d_in[12];
    float* out = (float*)d_out;

    cudaFuncSetAttribute(k_main, cudaFuncAttributeMaxDynamicSharedMemorySize, SMEM_BYTES);

    k_prep<<<En, En>>>(Bc_w, Bc_b, R_w, R_b);
    k_mask_init<<<(Bn * Mn + 255) / 256, 256>>>();
    k_mask_scatter<<<(Pn + 255) / 256, 256>>>(pad);
    k_main<<<GRID, TPB, SMEM_BYTES>>>(titems, citems, t_emb, c_emb,
                                      Ac_w, Ac_b, At_w, At_b, out);
}